// round 1
// baseline (speedup 1.0000x reference)
#include <cuda_runtime.h>
#include <math.h>

// ---------------- problem constants ----------------
#define B_   32
#define C_   192
#define H_   64
#define W_   64
#define HEADS_ 6
#define DH_  32
#define EMB_ 640
#define HID_ 768
#define GROUPS_ 32
#define SCALE_ 0.17677669529663688f  // 1/sqrt(32)

// ---------------- scratch (no allocations allowed) ----------------
__device__ float g_h  [B_*H_*W_*C_];   // BHWC, after GN1+adafm
__device__ float g_xa [B_*C_*H_*W_];   // BCHW, after attention residual
__device__ float g_h2 [B_*H_*W_*C_];   // BHWC, after GN2+adafm
__device__ float g_kmsa[B_*64];
__device__ float g_kmlp[B_*64];
__device__ float g_st1[B_*GROUPS_*2];
__device__ float g_st2[B_*GROUPS_*2];

__constant__ float c_c8[8] = {1.f, 0.70710678118654752f, 0.f, -0.70710678118654752f,
                              -1.f, -0.70710678118654752f, 0.f, 0.70710678118654752f};

// ---------------- K0: silu(t) @ ada_w^T + b  ->  8x8 circular-conv kernels ----------------
__global__ __launch_bounds__(128) void k0_ada(
    const float* __restrict__ t,
    const float* __restrict__ wm, const float* __restrict__ bm,
    const float* __restrict__ wl, const float* __restrict__ bl)
{
    int b = blockIdx.x, tid = threadIdx.x;
    __shared__ float st[EMB_];
    __shared__ float sv[80];
    for (int i = tid; i < EMB_; i += 128) {
        float v = t[b*EMB_ + i];
        st[i] = v / (1.f + expf(-v));
    }
    __syncthreads();
    if (tid < 80) {
        int j = tid % 40;
        const float* w = (tid < 40 ? wm : wl) + j*EMB_;
        float a0=0,a1=0,a2=0,a3=0;
        for (int i = 0; i < EMB_; i += 4) {
            a0 += st[i]*w[i];   a1 += st[i+1]*w[i+1];
            a2 += st[i+2]*w[i+2]; a3 += st[i+3]*w[i+3];
        }
        sv[tid] = (a0+a1)+(a2+a3) + (tid < 40 ? bm[j] : bl[j]);
    }
    __syncthreads();
    // k[du,dv] = (1/64) sum_{p,q} w_q S[p,q] cos(2pi(p du + q dv)/8)
    {
        int which = tid >> 6;      // 0: msa, 1: mlp
        int e = tid & 63, du = e >> 3, dv = e & 7;
        const float* S = sv + which*40;
        float acc = 0.f;
        #pragma unroll
        for (int p = 0; p < 8; p++)
            #pragma unroll
            for (int q = 0; q < 5; q++) {
                float wq = (q == 0 || q == 4) ? 1.f : 2.f;
                acc += wq * S[p*5 + q] * c_c8[(p*du + q*dv) & 7];
            }
        acc *= (1.f/64.f);
        if (which == 0) g_kmsa[b*64 + e] = acc;
        else            g_kmlp[b*64 + e] = acc;
    }
}

// ---------------- GroupNorm stats: one block per (b,g), 24576 contiguous floats ----------------
__global__ __launch_bounds__(256) void k_stats(const float* __restrict__ x, float* __restrict__ st)
{
    int bg = blockIdx.x, tid = threadIdx.x;
    const float* p = x + (size_t)bg * 24576;
    float s = 0.f, s2 = 0.f;
    for (int i = tid; i < 24576; i += 256) { float v = p[i]; s += v; s2 += v*v; }
    __shared__ float rs[8], rq[8];
    for (int o = 16; o; o >>= 1) {
        s  += __shfl_down_sync(0xffffffffu, s,  o);
        s2 += __shfl_down_sync(0xffffffffu, s2, o);
    }
    if ((tid & 31) == 0) { rs[tid>>5] = s; rq[tid>>5] = s2; }
    __syncthreads();
    if (tid == 0) {
        float S = 0.f, Q = 0.f;
        for (int i = 0; i < 8; i++) { S += rs[i]; Q += rq[i]; }
        float mu = S / 24576.f;
        float var = Q / 24576.f - mu*mu;
        st[bg*2]   = mu;
        st[bg*2+1] = rsqrtf(var + 1e-5f);
    }
}

// ---------------- GN apply + AdaFM (circular conv), BCHW -> BHWC ----------------
// grid (64 patches, 6 ch-chunks of 32, 32 batches), block 256
__global__ __launch_bounds__(256) void k_gn_ada(
    const float* __restrict__ x, const float* __restrict__ st,
    const float* __restrict__ gma, const float* __restrict__ bta,
    const float* __restrict__ kern, float* __restrict__ out)
{
    int pi = blockIdx.x, chunk = blockIdx.y, b = blockIdx.z;
    int pr = pi >> 3, pc = pi & 7;
    int tid = threadIdx.x;
    __shared__ float sp[32*64];
    __shared__ float kk[64];
    if (tid < 64) kk[tid] = kern[b*64 + tid];
    int ch0 = chunk * 32;
    for (int i = tid; i < 2048; i += 256) {
        int chL = i >> 6, rc = i & 63, r = rc >> 3, cc = rc & 7;
        int ch = ch0 + chL, g = ch / 6;
        float mu = st[(b*32+g)*2], rsd = st[(b*32+g)*2 + 1];
        float v = x[(size_t)(b*C_ + ch)*4096 + (pr*8 + r)*64 + pc*8 + cc];
        sp[i] = (v - mu) * rsd * gma[ch] + bta[ch];
    }
    __syncthreads();
    for (int i = tid; i < 2048; i += 256) {
        int chL = i >> 6, u = (i >> 3) & 7, v = i & 7;
        const float* spc = sp + chL*64;
        float acc = 0.f;
        #pragma unroll
        for (int a = 0; a < 8; a++) {
            int ku = ((u - a) & 7) * 8;
            #pragma unroll
            for (int bb = 0; bb < 8; bb++)
                acc += kk[ku + ((v - bb) & 7)] * spc[a*8 + bb];
        }
        int row = pr*8 + u, col = pc*8 + v;
        out[((size_t)(b*64 + row)*64 + col)*C_ + ch0 + chL] = acc;
    }
}

// ---------------- fused window attention + proj + reverse-roll + residual ----------------
// grid 2048 = b*64 + window, block 256, dynamic smem
__global__ __launch_bounds__(256) void k_attn(
    const float* __restrict__ h, const float* __restrict__ xin,
    const float* __restrict__ qkv_w, const float* __restrict__ qkv_b,
    const float* __restrict__ rpb, const float* __restrict__ proj_w,
    const float* __restrict__ proj_b, float* __restrict__ xa)
{
    extern __shared__ float sm[];
    float* xw   = sm;                 // 64*192 = 12288
    float* outw = xw + 12288;         // 64*193 = 12352
    float* q    = outw + 12352;       // 64*32  = 2048
    float* k    = q + 2048;           // 64*33  = 2112
    float* v    = k + 2112;           // 64*33  = 2112
    float* att  = v + 2112;           // 64*65  = 4160
    float* rb   = att + 4160;         // 240
    float* ws   = rb + 240;           // 96*193 = 18528
    __shared__ int lab[64];

    int tid = threadIdx.x;
    int blk = blockIdx.x;
    int b = blk >> 6, win = blk & 63;
    int wr = win >> 3, wc = win & 7;

    // load window tokens (rolled by -4,-4 via index math), BHWC contiguous per token
    for (int i = tid; i < 12288; i += 256) {
        int n = i / 192, c = i - n*192;
        int rr = (wr*8 + (n >> 3) + 4) & 63;
        int cc = (wc*8 + (n & 7) + 4) & 63;
        xw[i] = h[((size_t)(b*64 + rr)*64 + cc)*192 + c];
    }
    if (tid < 64) {
        int r = wr*8 + (tid >> 3), c = wc*8 + (tid & 7);
        int ra = (r < 56) ? 0 : (r < 60 ? 1 : 2);
        int ca = (c < 56) ? 0 : (c < 60 ? 1 : 2);
        lab[tid] = ra*3 + ca;
    }
    __syncthreads();

    for (int head = 0; head < HEADS_; head++) {
        // stage this head's 96 weight rows (q,k,v) + rel-pos bias slice
        for (int i = tid; i < 96*192; i += 256) {
            int rl = i / 192, ii = i - rl*192;
            int kind = rl >> 5, r = rl & 31;
            ws[rl*193 + ii] = qkv_w[(kind*192 + head*32 + r)*192 + ii];
        }
        if (tid < 225) rb[tid] = rpb[tid*6 + head];
        __syncthreads();
        // qkv: 3*64*32 outputs, K=192
        for (int o = tid; o < 6144; o += 256) {
            int kind = o >> 11, rd = o & 2047, n = rd >> 5, d = rd & 31;
            const float* wp = ws + (kind*32 + d)*193;
            const float* xp = xw + n*192;
            float a0=0,a1=0,a2=0,a3=0;
            #pragma unroll 4
            for (int i = 0; i < 192; i += 4) {
                a0 += xp[i]*wp[i];     a1 += xp[i+1]*wp[i+1];
                a2 += xp[i+2]*wp[i+2]; a3 += xp[i+3]*wp[i+3];
            }
            float acc = (a0+a1)+(a2+a3) + qkv_b[kind*192 + head*32 + d];
            if (kind == 0)      q[n*32 + d] = acc * SCALE_;
            else if (kind == 1) k[n*33 + d] = acc;
            else                v[n*33 + d] = acc;
        }
        __syncthreads();
        // logits + bias + mask
        for (int e = tid; e < 4096; e += 256) {
            int n = e >> 6, m = e & 63;
            const float* qp = q + n*32;
            const float* kp = k + m*33;
            float a0=0,a1=0;
            #pragma unroll
            for (int d = 0; d < 32; d += 2) { a0 += qp[d]*kp[d]; a1 += qp[d+1]*kp[d+1]; }
            int di = (n >> 3) - (m >> 3) + 7;
            int dj = (n & 7) - (m & 7) + 7;
            float val = a0 + a1 + rb[di*15 + dj];
            if (lab[n] != lab[m]) val -= 100.f;
            att[n*65 + m] = val;
        }
        __syncthreads();
        // softmax (one row per thread, 64 rows)
        if (tid < 64) {
            float* ar = att + tid*65;
            float mx = ar[0];
            for (int m2 = 1; m2 < 64; m2++) mx = fmaxf(mx, ar[m2]);
            float s = 0.f;
            for (int m2 = 0; m2 < 64; m2++) { float ex = expf(ar[m2] - mx); ar[m2] = ex; s += ex; }
            float inv = 1.f / s;
            for (int m2 = 0; m2 < 64; m2++) ar[m2] *= inv;
        }
        __syncthreads();
        // AV
        for (int o = tid; o < 2048; o += 256) {
            int n = o >> 5, d = o & 31;
            const float* ap = att + n*65;
            float a0=0,a1=0;
            #pragma unroll 4
            for (int m2 = 0; m2 < 64; m2 += 2) {
                a0 += ap[m2]  * v[m2*33 + d];
                a1 += ap[m2+1]* v[(m2+1)*33 + d];
            }
            outw[n*193 + head*32 + d] = a0 + a1;
        }
        __syncthreads();
    }
    // proj + residual + reverse roll, write BCHW
    for (int o = tid; o < 12288; o += 256) {
        int n = o & 63, co = o >> 6;
        const float* wp = proj_w + co*192;
        const float* op = outw + n*193;
        float a0=0,a1=0,a2=0,a3=0;
        #pragma unroll 4
        for (int i = 0; i < 192; i += 4) {
            a0 += op[i]*wp[i];     a1 += op[i+1]*wp[i+1];
            a2 += op[i+2]*wp[i+2]; a3 += op[i+3]*wp[i+3];
        }
        float acc = (a0+a1)+(a2+a3) + proj_b[co];
        int fr = (wr*8 + (n >> 3) + 4) & 63;
        int fc = (wc*8 + (n & 7) + 4) & 63;
        size_t oi = ((size_t)(b*192 + co)*64 + fr)*64 + fc;
        xa[oi] = xin[oi] + acc;
    }
}

// ---------------- fused MLP: fc1 -> exact gelu -> fc2 + residual ----------------
// grid 2048 = b*64 + row, block 256, dynamic smem
__global__ __launch_bounds__(256) void k_mlp(
    const float* __restrict__ h2, const float* __restrict__ xa,
    const float* __restrict__ fc1_w, const float* __restrict__ fc1_b,
    const float* __restrict__ fc2_w, const float* __restrict__ fc2_b,
    float* __restrict__ out)
{
    extern __shared__ float sm[];
    float* xt  = sm;            // 64*192 = 12288
    float* acc = xt + 12288;    // 64*193 = 12352
    float* hid = acc + 12352;   // 64*97  = 6208
    float* wb  = hid + 6208;    // max(96*193, 192*97) = 18624
    int tid = threadIdx.x;
    int blk = blockIdx.x;
    int b = blk >> 6, hh = blk & 63;
    const float* src = h2 + (size_t)(b*64 + hh)*64*192;
    for (int i = tid; i < 12288; i += 256) xt[i] = src[i];
    for (int i = tid; i < 12352; i += 256) acc[i] = 0.f;
    __syncthreads();
    for (int chunk = 0; chunk < 8; chunk++) {
        // stage fc1 chunk (96 x 192)
        for (int i = tid; i < 96*192; i += 256) {
            int j = i / 192, ii = i - j*192;
            wb[j*193 + ii] = fc1_w[(chunk*96 + j)*192 + ii];
        }
        __syncthreads();
        for (int o = tid; o < 6144; o += 256) {
            int px = o / 96, j = o - px*96;
            const float* wp = wb + j*193;
            const float* xp = xt + px*192;
            float a0=0,a1=0,a2=0,a3=0;
            #pragma unroll 4
            for (int i = 0; i < 192; i += 4) {
                a0 += xp[i]*wp[i];     a1 += xp[i+1]*wp[i+1];
                a2 += xp[i+2]*wp[i+2]; a3 += xp[i+3]*wp[i+3];
            }
            float val = (a0+a1)+(a2+a3) + fc1_b[chunk*96 + j];
            hid[px*97 + j] = 0.5f * val * (1.f + erff(val * 0.70710678118654752f));
        }
        __syncthreads();
        // stage fc2 chunk (192 x 96)
        for (int i = tid; i < 192*96; i += 256) {
            int co = i / 96, j = i - co*96;
            wb[co*97 + j] = fc2_w[co*768 + chunk*96 + j];
        }
        __syncthreads();
        for (int o = tid; o < 12288; o += 256) {
            int px = o / 192, co = o - px*192;
            const float* wp = wb + co*97;
            const float* hp = hid + px*97;
            float a0=0,a1=0;
            #pragma unroll 4
            for (int j = 0; j < 96; j += 2) { a0 += hp[j]*wp[j]; a1 += hp[j+1]*wp[j+1]; }
            acc[px*193 + co] += a0 + a1;
        }
        __syncthreads();
    }
    for (int o = tid; o < 12288; o += 256) {
        int co = o >> 6, ww = o & 63;
        size_t gi = ((size_t)(b*192 + co)*64 + hh)*64 + ww;
        out[gi] = xa[gi] + acc[ww*193 + co] + fc2_b[co];
    }
}

// ---------------- launcher ----------------
extern "C" void kernel_launch(void* const* d_in, const int* in_sizes, int n_in,
                              void* d_out, int out_size)
{
    const float* x        = (const float*)d_in[0];
    const float* t        = (const float*)d_in[1];
    const float* n1_w     = (const float*)d_in[2];
    const float* n1_b     = (const float*)d_in[3];
    const float* qkv_w    = (const float*)d_in[4];
    const float* qkv_b    = (const float*)d_in[5];
    const float* rpb      = (const float*)d_in[6];
    const float* proj_w   = (const float*)d_in[7];
    const float* proj_b   = (const float*)d_in[8];
    const float* n2_w     = (const float*)d_in[9];
    const float* n2_b     = (const float*)d_in[10];
    const float* fc1_w    = (const float*)d_in[11];
    const float* fc1_b    = (const float*)d_in[12];
    const float* fc2_w    = (const float*)d_in[13];
    const float* fc2_b    = (const float*)d_in[14];
    const float* ada_msa_w = (const float*)d_in[15];
    const float* ada_msa_b = (const float*)d_in[16];
    const float* ada_mlp_w = (const float*)d_in[17];
    const float* ada_mlp_b = (const float*)d_in[18];
    float* out = (float*)d_out;

    float *p_h, *p_xa, *p_h2, *p_kmsa, *p_kmlp, *p_st1, *p_st2;
    cudaGetSymbolAddress((void**)&p_h,    g_h);
    cudaGetSymbolAddress((void**)&p_xa,   g_xa);
    cudaGetSymbolAddress((void**)&p_h2,   g_h2);
    cudaGetSymbolAddress((void**)&p_kmsa, g_kmsa);
    cudaGetSymbolAddress((void**)&p_kmlp, g_kmlp);
    cudaGetSymbolAddress((void**)&p_st1,  g_st1);
    cudaGetSymbolAddress((void**)&p_st2,  g_st2);

    cudaFuncSetAttribute(k_attn, cudaFuncAttributeMaxDynamicSharedMemorySize, 215360);
    cudaFuncSetAttribute(k_mlp,  cudaFuncAttributeMaxDynamicSharedMemorySize, 197888);

    k0_ada<<<32, 128>>>(t, ada_msa_w, ada_msa_b, ada_mlp_w, ada_mlp_b);
    k_stats<<<1024, 256>>>(x, p_st1);
    k_gn_ada<<<dim3(64, 6, 32), 256>>>(x, p_st1, n1_w, n1_b, p_kmsa, p_h);
    k_attn<<<2048, 256, 215360>>>(p_h, x, qkv_w, qkv_b, rpb, proj_w, proj_b, p_xa);
    k_stats<<<1024, 256>>>(p_xa, p_st2);
    k_gn_ada<<<dim3(64, 6, 32), 256>>>(p_xa, p_st2, n2_w, n2_b, p_kmlp, p_h2);
    k_mlp<<<2048, 256, 197888>>>(p_h2, p_xa, fc1_w, fc1_b, fc2_w, fc2_b, out);
}

// round 2
// speedup vs baseline: 3.3805x; 3.3805x over previous
#include <cuda_runtime.h>
#include <math.h>

#define B_   32
#define C_   192
#define EMB_ 640
#define SCALE_ 0.17677669529663688f  // 1/sqrt(32)

// ---------------- scratch ----------------
__device__ float g_h  [32*64*64*192];   // BHWC after GN1+adafm
__device__ float g_xa [32*192*64*64];   // BCHW after attention residual
__device__ float g_h2 [32*64*64*192];   // BHWC after GN2+adafm
__device__ float g_kmsa[32*64];
__device__ float g_kmlp[32*64];
__device__ float g_st1[32*32*2];
__device__ float g_st2[32*32*2];
// K-major (transposed) weights
__device__ float g_qkvT[6*192*96];      // [head][k=192][j=kind*32+d]
__device__ float g_pT  [192*192];       // [k][co]
__device__ float g_f1T [192*768];       // [k][j]
__device__ float g_f2T [768*192];       // [j][co]

__constant__ float c_c8[8] = {1.f, 0.70710678118654752f, 0.f, -0.70710678118654752f,
                              -1.f, -0.70710678118654752f, 0.f, 0.70710678118654752f};

// ---------------- weight transposition (cheap, per launch) ----------------
__global__ __launch_bounds__(256) void k_prep(
    const float* __restrict__ qkv_w, const float* __restrict__ proj_w,
    const float* __restrict__ fc1_w, const float* __restrict__ fc2_w)
{
    int idx = blockIdx.x * 256 + threadIdx.x;
    if (idx < 110592) {
        int h = idx / 18432, r = idx % 18432;
        int i = r / 96, j = r % 96;
        int kind = j >> 5, d = j & 31;
        g_qkvT[idx] = qkv_w[(kind*192 + h*32 + d)*192 + i];
    } else if (idx < 147456) {
        int r = idx - 110592;
        int i = r / 192, co = r % 192;
        g_pT[r] = proj_w[co*192 + i];
    } else if (idx < 294912) {
        int r = idx - 147456;
        int i = r / 768, j = r % 768;
        g_f1T[r] = fc1_w[j*192 + i];
    } else if (idx < 442368) {
        int r = idx - 294912;
        int j = r / 192, co = r % 192;
        g_f2T[r] = fc2_w[co*768 + j];
    }
}

// ---------------- K0: silu(t) -> adafm 8x8 circular-conv kernels ----------------
__global__ __launch_bounds__(128) void k0_ada(
    const float* __restrict__ t,
    const float* __restrict__ wm, const float* __restrict__ bm,
    const float* __restrict__ wl, const float* __restrict__ bl)
{
    int b = blockIdx.x, tid = threadIdx.x;
    __shared__ float st[EMB_];
    __shared__ float sv[80];
    for (int i = tid; i < EMB_; i += 128) {
        float v = t[b*EMB_ + i];
        st[i] = v / (1.f + expf(-v));
    }
    __syncthreads();
    if (tid < 80) {
        int j = tid % 40;
        const float* w = (tid < 40 ? wm : wl) + j*EMB_;
        float a0=0,a1=0,a2=0,a3=0;
        for (int i = 0; i < EMB_; i += 4) {
            a0 += st[i]*w[i];   a1 += st[i+1]*w[i+1];
            a2 += st[i+2]*w[i+2]; a3 += st[i+3]*w[i+3];
        }
        sv[tid] = (a0+a1)+(a2+a3) + (tid < 40 ? bm[j] : bl[j]);
    }
    __syncthreads();
    {
        int which = tid >> 6;
        int e = tid & 63, du = e >> 3, dv = e & 7;
        const float* S = sv + which*40;
        float acc = 0.f;
        #pragma unroll
        for (int p = 0; p < 8; p++)
            #pragma unroll
            for (int q = 0; q < 5; q++) {
                float wq = (q == 0 || q == 4) ? 1.f : 2.f;
                acc += wq * S[p*5 + q] * c_c8[(p*du + q*dv) & 7];
            }
        acc *= (1.f/64.f);
        if (which == 0) g_kmsa[b*64 + e] = acc;
        else            g_kmlp[b*64 + e] = acc;
    }
}

// ---------------- GroupNorm stats ----------------
__global__ __launch_bounds__(256) void k_stats(const float* __restrict__ x, float* __restrict__ st)
{
    int bg = blockIdx.x, tid = threadIdx.x;
    const float* p = x + (size_t)bg * 24576;
    float s = 0.f, s2 = 0.f;
    for (int i = tid; i < 24576; i += 256) { float v = p[i]; s += v; s2 += v*v; }
    __shared__ float rs[8], rq[8];
    for (int o = 16; o; o >>= 1) {
        s  += __shfl_down_sync(0xffffffffu, s,  o);
        s2 += __shfl_down_sync(0xffffffffu, s2, o);
    }
    if ((tid & 31) == 0) { rs[tid>>5] = s; rq[tid>>5] = s2; }
    __syncthreads();
    if (tid == 0) {
        float S = 0.f, Q = 0.f;
        for (int i = 0; i < 8; i++) { S += rs[i]; Q += rq[i]; }
        float mu = S / 24576.f;
        float var = Q / 24576.f - mu*mu;
        st[bg*2]   = mu;
        st[bg*2+1] = rsqrtf(var + 1e-5f);
    }
}

// ---------------- GN apply + AdaFM circular conv, BCHW -> BHWC ----------------
__global__ __launch_bounds__(256) void k_gn_ada(
    const float* __restrict__ x, const float* __restrict__ st,
    const float* __restrict__ gma, const float* __restrict__ bta,
    const float* __restrict__ kern, float* __restrict__ out)
{
    int pi = blockIdx.x, chunk = blockIdx.y, b = blockIdx.z;
    int pr = pi >> 3, pc = pi & 7;
    int tid = threadIdx.x;
    __shared__ float sp[32*64];
    __shared__ float kk[64];
    if (tid < 64) kk[tid] = kern[b*64 + tid];
    int ch0 = chunk * 32;
    for (int i = tid; i < 2048; i += 256) {
        int chL = i >> 6, rc = i & 63, r = rc >> 3, cc = rc & 7;
        int ch = ch0 + chL, g = ch / 6;
        float mu = st[(b*32+g)*2], rsd = st[(b*32+g)*2 + 1];
        float v = x[(size_t)(b*192 + ch)*4096 + (pr*8 + r)*64 + pc*8 + cc];
        sp[i] = (v - mu) * rsd * gma[ch] + bta[ch];
    }
    __syncthreads();
    for (int i = tid; i < 2048; i += 256) {
        int chL = i >> 6, u = (i >> 3) & 7, v = i & 7;
        const float* spc = sp + chL*64;
        float acc = 0.f;
        #pragma unroll
        for (int a = 0; a < 8; a++) {
            int ku = ((u - a) & 7) * 8;
            #pragma unroll
            for (int bb = 0; bb < 8; bb++)
                acc += kk[ku + ((v - bb) & 7)] * spc[a*8 + bb];
        }
        int row = pr*8 + u, col = pc*8 + v;
        out[((size_t)(b*64 + row)*64 + col)*192 + ch0 + chL] = acc;
    }
}

// ---------------- fused window attention (register-tiled) ----------------
// grid 2048, block 256
__global__ __launch_bounds__(256) void k_attn(
    const float* __restrict__ h, const float* __restrict__ xin,
    const float* __restrict__ qkvT, const float* __restrict__ qkv_b,
    const float* __restrict__ rpb, const float* __restrict__ pT,
    const float* __restrict__ proj_b, float* __restrict__ xa)
{
    extern __shared__ float sm[];
    float* xw   = sm;              // [64][193]   12352
    float* wb   = xw + 12352;      // [192][96]   18432
    float* qT   = wb + 18432;      // [32][64]    2048
    float* kT   = qT + 2048;       // [32][64]    2048
    float* vS   = kT + 2048;       // [64][32]    2048
    float* A    = vS + 2048;       // [64][65]    4160
    float* outT = A + 4160;        // [192][64]   12288
    float* rb   = outT + 12288;    // 225
    __shared__ int lab[64];

    int tid = threadIdx.x;
    int b = blockIdx.x >> 6, win = blockIdx.x & 63;
    int wr = win >> 3, wc = win & 7;

    for (int i = tid; i < 12288; i += 256) {
        int n = i / 192, c = i - n*192;
        int rr = (wr*8 + (n >> 3) + 4) & 63;
        int cc = (wc*8 + (n & 7) + 4) & 63;
        xw[n*193 + c] = h[((size_t)((b*64 + rr)*64 + cc))*192 + c];
    }
    if (tid < 64) {
        int r = wr*8 + (tid >> 3), c = wc*8 + (tid & 7);
        int ra = (r < 56) ? 0 : (r < 60 ? 1 : 2);
        int ca = (c < 56) ? 0 : (c < 60 ? 1 : 2);
        lab[tid] = ra*3 + ca;
    }

    int mt = tid & 15, nt = tid >> 4;
    int m0 = mt * 4;

    for (int head = 0; head < 6; head++) {
        __syncthreads();
        {   // stage this head's K-major qkv weights (float4 copy)
            const float4* srcw = (const float4*)(qkvT + head*18432);
            float4* dstw = (float4*)wb;
            #pragma unroll
            for (int i = 0; i < 18; i++) dstw[tid + i*256] = srcw[tid + i*256];
        }
        if (tid < 225) rb[tid] = rpb[tid*6 + head];
        __syncthreads();

        // ---- QKV GEMM: 64x96, K=192, thread tile 4x6 ----
        {
            int j0 = nt * 6;
            float acc[4][6];
            #pragma unroll
            for (int i = 0; i < 4; i++)
                #pragma unroll
                for (int j = 0; j < 6; j++) acc[i][j] = 0.f;
            #pragma unroll 2
            for (int k2 = 0; k2 < 192; k2++) {
                float xv[4];
                #pragma unroll
                for (int i = 0; i < 4; i++) xv[i] = xw[(m0+i)*193 + k2];
                float2 w0 = *(const float2*)&wb[k2*96 + j0];
                float2 w1 = *(const float2*)&wb[k2*96 + j0 + 2];
                float2 w2 = *(const float2*)&wb[k2*96 + j0 + 4];
                float wv[6] = {w0.x, w0.y, w1.x, w1.y, w2.x, w2.y};
                #pragma unroll
                for (int i = 0; i < 4; i++)
                    #pragma unroll
                    for (int j = 0; j < 6; j++) acc[i][j] += xv[i] * wv[j];
            }
            #pragma unroll
            for (int jj = 0; jj < 6; jj++) {
                int j = j0 + jj, kind = j >> 5, d = j & 31;
                float bias = qkv_b[kind*192 + head*32 + d];
                #pragma unroll
                for (int i = 0; i < 4; i++) {
                    float val = acc[i][jj] + bias;
                    if (kind == 0)      qT[d*64 + m0 + i] = val * SCALE_;
                    else if (kind == 1) kT[d*64 + m0 + i] = val;
                    else                vS[(m0+i)*32 + d] = val;
                }
            }
        }
        __syncthreads();

        // ---- logits: 64x64, K=32, thread tile 4x4 ----
        {
            int n0 = mt * 4, mm0 = nt * 4;
            float acc[4][4];
            #pragma unroll
            for (int i = 0; i < 4; i++)
                #pragma unroll
                for (int j = 0; j < 4; j++) acc[i][j] = 0.f;
            #pragma unroll 4
            for (int d = 0; d < 32; d++) {
                float4 qv = *(const float4*)&qT[d*64 + n0];
                float4 kv = *(const float4*)&kT[d*64 + mm0];
                float qa[4] = {qv.x, qv.y, qv.z, qv.w};
                float ka[4] = {kv.x, kv.y, kv.z, kv.w};
                #pragma unroll
                for (int i = 0; i < 4; i++)
                    #pragma unroll
                    for (int j = 0; j < 4; j++) acc[i][j] += qa[i] * ka[j];
            }
            #pragma unroll
            for (int i = 0; i < 4; i++)
                #pragma unroll
                for (int j = 0; j < 4; j++) {
                    int n = n0 + i, m = mm0 + j;
                    int di = (n >> 3) - (m >> 3) + 7;
                    int dj = (n & 7) - (m & 7) + 7;
                    float v = acc[i][j] + rb[di*15 + dj];
                    if (lab[n] != lab[m]) v -= 100.f;
                    A[n*65 + m] = v;
                }
        }
        __syncthreads();

        // ---- softmax: one row per thread ----
        if (tid < 64) {
            float* ar = A + tid*65;
            float mx = ar[0];
            #pragma unroll 4
            for (int m2 = 1; m2 < 64; m2++) mx = fmaxf(mx, ar[m2]);
            float s = 0.f;
            #pragma unroll 4
            for (int m2 = 0; m2 < 64; m2++) { float ex = expf(ar[m2] - mx); ar[m2] = ex; s += ex; }
            float inv = 1.f / s;
            #pragma unroll 4
            for (int m2 = 0; m2 < 64; m2++) ar[m2] *= inv;
        }
        __syncthreads();

        // ---- AV: 64x32, K=64, thread tile 4x2 ----
        {
            int n0 = mt * 4, d0 = nt * 2;
            float acc[4][2];
            #pragma unroll
            for (int i = 0; i < 4; i++) { acc[i][0] = 0.f; acc[i][1] = 0.f; }
            #pragma unroll 2
            for (int m2 = 0; m2 < 64; m2++) {
                float2 vv = *(const float2*)&vS[m2*32 + d0];
                #pragma unroll
                for (int i = 0; i < 4; i++) {
                    float a = A[(n0+i)*65 + m2];
                    acc[i][0] += a * vv.x;
                    acc[i][1] += a * vv.y;
                }
            }
            #pragma unroll
            for (int i = 0; i < 4; i++)
                #pragma unroll
                for (int j = 0; j < 2; j++)
                    outT[(head*32 + d0 + j)*64 + n0 + i] = acc[i][j];
        }
    }

    // ---- proj + residual + reverse roll (2 chunks of 96 cols) ----
    for (int cch = 0; cch < 2; cch++) {
        __syncthreads();
        {
            const float* srcp = pT + cch*96;
            for (int i4 = tid; i4 < 4608; i4 += 256) {
                int i = i4 / 24, j4 = i4 % 24;
                *(float4*)&wb[i*96 + j4*4] = *(const float4*)&srcp[i*192 + j4*4];
            }
        }
        __syncthreads();
        int j0 = nt * 6;
        float acc[4][6];
        #pragma unroll
        for (int i = 0; i < 4; i++)
            #pragma unroll
            for (int j = 0; j < 6; j++) acc[i][j] = 0.f;
        #pragma unroll 2
        for (int k2 = 0; k2 < 192; k2++) {
            float4 xv4 = *(const float4*)&outT[k2*64 + m0];
            float xv[4] = {xv4.x, xv4.y, xv4.z, xv4.w};
            float2 w0 = *(const float2*)&wb[k2*96 + j0];
            float2 w1 = *(const float2*)&wb[k2*96 + j0 + 2];
            float2 w2 = *(const float2*)&wb[k2*96 + j0 + 4];
            float wv[6] = {w0.x, w0.y, w1.x, w1.y, w2.x, w2.y};
            #pragma unroll
            for (int i = 0; i < 4; i++)
                #pragma unroll
                for (int j = 0; j < 6; j++) acc[i][j] += xv[i] * wv[j];
        }
        #pragma unroll
        for (int jj = 0; jj < 6; jj++) {
            int co = cch*96 + j0 + jj;
            float bias = proj_b[co];
            #pragma unroll
            for (int i = 0; i < 4; i++) {
                int n = m0 + i;
                int fr = (wr*8 + (n >> 3) + 4) & 63;
                int fc = (wc*8 + (n & 7) + 4) & 63;
                size_t gi = ((size_t)((b*192 + co)*64 + fr))*64 + fc;
                xa[gi] = xin[gi] + acc[i][jj] + bias;
            }
        }
    }
}

// ---------------- fused MLP (register-tiled) ----------------
// grid 2048, block 256
__global__ __launch_bounds__(256) void k_mlp(
    const float* __restrict__ h2, const float* __restrict__ xa,
    const float* __restrict__ f1T, const float* __restrict__ fc1_b,
    const float* __restrict__ f2T, const float* __restrict__ fc2_b,
    float* __restrict__ out)
{
    extern __shared__ float sm[];
    float* xt   = sm;            // [64][193]  12352
    float* hidT = xt + 12352;    // [96][64]   6144
    float* wb   = hidT + 6144;   // 18432
    int tid = threadIdx.x;
    int b = blockIdx.x >> 6, hh = blockIdx.x & 63;
    const float* src = h2 + ((size_t)(b*64 + hh))*64*192;
    for (int i = tid; i < 12288; i += 256) {
        int n = i / 192, c = i - n*192;
        xt[n*193 + c] = src[i];
    }
    int mt = tid & 15, ct = tid >> 4;
    int m0 = mt * 4;
    int co0 = ct * 12;
    float oacc[4][12];
    #pragma unroll
    for (int i = 0; i < 4; i++)
        #pragma unroll
        for (int j = 0; j < 12; j++) oacc[i][j] = 0.f;

    for (int chunk = 0; chunk < 8; chunk++) {
        __syncthreads();
        // stage fc1 chunk [192][96] (K-major)
        for (int i4 = tid; i4 < 4608; i4 += 256) {
            int k = i4 / 24, j4 = i4 % 24;
            *(float4*)&wb[k*96 + j4*4] = *(const float4*)&f1T[k*768 + chunk*96 + j4*4];
        }
        __syncthreads();
        // GEMM1: 64x96, K=192, tile 4x6 -> gelu -> hidT
        {
            int j0 = ct * 6;
            float acc[4][6];
            #pragma unroll
            for (int i = 0; i < 4; i++)
                #pragma unroll
                for (int j = 0; j < 6; j++) acc[i][j] = 0.f;
            #pragma unroll 2
            for (int k2 = 0; k2 < 192; k2++) {
                float xv[4];
                #pragma unroll
                for (int i = 0; i < 4; i++) xv[i] = xt[(m0+i)*193 + k2];
                float2 w0 = *(const float2*)&wb[k2*96 + j0];
                float2 w1 = *(const float2*)&wb[k2*96 + j0 + 2];
                float2 w2 = *(const float2*)&wb[k2*96 + j0 + 4];
                float wv[6] = {w0.x, w0.y, w1.x, w1.y, w2.x, w2.y};
                #pragma unroll
                for (int i = 0; i < 4; i++)
                    #pragma unroll
                    for (int j = 0; j < 6; j++) acc[i][j] += xv[i] * wv[j];
            }
            #pragma unroll
            for (int jj = 0; jj < 6; jj++) {
                float bias = fc1_b[chunk*96 + j0 + jj];
                #pragma unroll
                for (int i = 0; i < 4; i++) {
                    float val = acc[i][jj] + bias;
                    val = 0.5f * val * (1.f + erff(val * 0.70710678118654752f));
                    hidT[(j0+jj)*64 + m0 + i] = val;
                }
            }
        }
        __syncthreads();
        // stage fc2 chunk [96][192] (contiguous block)
        {
            const float4* s4 = (const float4*)(f2T + chunk*96*192);
            float4* d4 = (float4*)wb;
            #pragma unroll
            for (int i = 0; i < 18; i++) d4[tid + i*256] = s4[tid + i*256];
        }
        __syncthreads();
        // GEMM2: 64x192, K=96, tile 4x12 accumulate in regs
        #pragma unroll 2
        for (int jL = 0; jL < 96; jL++) {
            float4 xv4 = *(const float4*)&hidT[jL*64 + m0];
            float xv[4] = {xv4.x, xv4.y, xv4.z, xv4.w};
            float4 wA = *(const float4*)&wb[jL*192 + co0];
            float4 wBv = *(const float4*)&wb[jL*192 + co0 + 4];
            float4 wC = *(const float4*)&wb[jL*192 + co0 + 8];
            float wv[12] = {wA.x, wA.y, wA.z, wA.w, wBv.x, wBv.y, wBv.z, wBv.w,
                            wC.x, wC.y, wC.z, wC.w};
            #pragma unroll
            for (int i = 0; i < 4; i++)
                #pragma unroll
                for (int j = 0; j < 12; j++) oacc[i][j] += xv[i] * wv[j];
        }
    }
    // epilogue: bias + residual, BCHW
    #pragma unroll
    for (int j = 0; j < 12; j++) {
        int co = co0 + j;
        float bias = fc2_b[co];
        #pragma unroll
        for (int i = 0; i < 4; i++) {
            size_t gi = ((size_t)((b*192 + co)*64 + hh))*64 + m0 + i;
            out[gi] = xa[gi] + oacc[i][j] + bias;
        }
    }
}

// ---------------- launcher ----------------
extern "C" void kernel_launch(void* const* d_in, const int* in_sizes, int n_in,
                              void* d_out, int out_size)
{
    const float* x        = (const float*)d_in[0];
    const float* t        = (const float*)d_in[1];
    const float* n1_w     = (const float*)d_in[2];
    const float* n1_b     = (const float*)d_in[3];
    const float* qkv_w    = (const float*)d_in[4];
    const float* qkv_b    = (const float*)d_in[5];
    const float* rpb      = (const float*)d_in[6];
    const float* proj_w   = (const float*)d_in[7];
    const float* proj_b   = (const float*)d_in[8];
    const float* n2_w     = (const float*)d_in[9];
    const float* n2_b     = (const float*)d_in[10];
    const float* fc1_w    = (const float*)d_in[11];
    const float* fc1_b    = (const float*)d_in[12];
    const float* fc2_w    = (const float*)d_in[13];
    const float* fc2_b    = (const float*)d_in[14];
    const float* ada_msa_w = (const float*)d_in[15];
    const float* ada_msa_b = (const float*)d_in[16];
    const float* ada_mlp_w = (const float*)d_in[17];
    const float* ada_mlp_b = (const float*)d_in[18];
    float* out = (float*)d_out;

    float *p_h, *p_xa, *p_h2, *p_kmsa, *p_kmlp, *p_st1, *p_st2;
    float *p_qkvT, *p_pT, *p_f1T, *p_f2T;
    cudaGetSymbolAddress((void**)&p_h,    g_h);
    cudaGetSymbolAddress((void**)&p_xa,   g_xa);
    cudaGetSymbolAddress((void**)&p_h2,   g_h2);
    cudaGetSymbolAddress((void**)&p_kmsa, g_kmsa);
    cudaGetSymbolAddress((void**)&p_kmlp, g_kmlp);
    cudaGetSymbolAddress((void**)&p_st1,  g_st1);
    cudaGetSymbolAddress((void**)&p_st2,  g_st2);
    cudaGetSymbolAddress((void**)&p_qkvT, g_qkvT);
    cudaGetSymbolAddress((void**)&p_pT,   g_pT);
    cudaGetSymbolAddress((void**)&p_f1T,  g_f1T);
    cudaGetSymbolAddress((void**)&p_f2T,  g_f2T);

    cudaFuncSetAttribute(k_attn, cudaFuncAttributeMaxDynamicSharedMemorySize, 214416);
    cudaFuncSetAttribute(k_mlp,  cudaFuncAttributeMaxDynamicSharedMemorySize, 147712);

    k_prep<<<1728, 256>>>(qkv_w, proj_w, fc1_w, fc2_w);
    k0_ada<<<32, 128>>>(t, ada_msa_w, ada_msa_b, ada_mlp_w, ada_mlp_b);
    k_stats<<<1024, 256>>>(x, p_st1);
    k_gn_ada<<<dim3(64, 6, 32), 256>>>(x, p_st1, n1_w, n1_b, p_kmsa, p_h);
    k_attn<<<2048, 256, 214416>>>(p_h, x, p_qkvT, qkv_b, rpb, p_pT, proj_b, p_xa);
    k_stats<<<1024, 256>>>(p_xa, p_st2);
    k_gn_ada<<<dim3(64, 6, 32), 256>>>(p_xa, p_st2, n2_w, n2_b, p_kmlp, p_h2);
    k_mlp<<<2048, 256, 147712>>>(p_h2, p_xa, p_f1T, fc1_b, p_f2T, fc2_b, out);
}

// round 6
// speedup vs baseline: 4.2091x; 1.2451x over previous
#include <cuda_runtime.h>
#include <math.h>

#define B_   32
#define C_   192
#define EMB_ 640
#define SCALE_ 0.17677669529663688f  // 1/sqrt(32)

typedef unsigned long long ull;

// ---------------- packed f32x2 helpers (FFMA2 path) ----------------
__device__ __forceinline__ ull dup2(float x) {
    ull r; asm("mov.b64 %0, {%1, %1};" : "=l"(r) : "f"(x)); return r;
}
__device__ __forceinline__ void fma2(ull& d, ull a, ull b) {
    asm("fma.rn.f32x2 %0, %1, %2, %0;" : "+l"(d) : "l"(a), "l"(b));
}
__device__ __forceinline__ void unpk(ull v, float& lo, float& hi) {
    asm("mov.b64 {%0, %1}, %2;" : "=f"(lo), "=f"(hi) : "l"(v));
}

// ---------------- scratch ----------------
__device__ float g_h  [32*64*64*192];   // BHWC after GN1+adafm
__device__ float g_xa [32*192*64*64];   // BCHW after attention residual
__device__ float g_h2 [32*64*64*192];   // BHWC after GN2+adafm
__device__ float g_kc1[32*4096];        // circulant KcT[f][e] per batch (msa)
__device__ float g_kc2[32*4096];        // (mlp)
__device__ float g_st1[32*32*2];
__device__ float g_st2[32*32*2];
__device__ float g_qkvT[6*192*96];      // [head][k=192][j]
__device__ float g_pT  [192*192];       // [k][co]
__device__ float g_f1T [192*768];       // [k][j]
__device__ float g_f2T [768*192];       // [j][co]

__constant__ float c_c8[8] = {1.f, 0.70710678118654752f, 0.f, -0.70710678118654752f,
                              -1.f, -0.70710678118654752f, 0.f, 0.70710678118654752f};

// ---------------- weight transposition ----------------
__global__ __launch_bounds__(256) void k_prep(
    const float* __restrict__ qkv_w, const float* __restrict__ proj_w,
    const float* __restrict__ fc1_w, const float* __restrict__ fc2_w)
{
    int idx = blockIdx.x * 256 + threadIdx.x;
    if (idx < 110592) {
        int h = idx / 18432, r = idx % 18432;
        int i = r / 96, j = r % 96;
        int kind = j >> 5, d = j & 31;
        g_qkvT[idx] = qkv_w[(kind*192 + h*32 + d)*192 + i];
    } else if (idx < 147456) {
        int r = idx - 110592;
        int i = r / 192, co = r % 192;
        g_pT[r] = proj_w[co*192 + i];
    } else if (idx < 294912) {
        int r = idx - 147456;
        int i = r / 768, j = r % 768;
        g_f1T[r] = fc1_w[j*192 + i];
    } else if (idx < 442368) {
        int r = idx - 294912;
        int j = r / 192, co = r % 192;
        g_f2T[r] = fc2_w[co*768 + j];
    }
}

// ---------------- K0: silu(t) -> adafm kernels -> circulant matrices ----------------
__global__ __launch_bounds__(128) void k0_ada(
    const float* __restrict__ t,
    const float* __restrict__ wm, const float* __restrict__ bm,
    const float* __restrict__ wl, const float* __restrict__ bl)
{
    int b = blockIdx.x, tid = threadIdx.x;
    __shared__ float st[EMB_];
    __shared__ float sv[80];
    __shared__ float kk[2][64];
    for (int i = tid; i < EMB_; i += 128) {
        float v = t[b*EMB_ + i];
        st[i] = v / (1.f + expf(-v));
    }
    __syncthreads();
    if (tid < 80) {
        int j = tid % 40;
        const float* w = (tid < 40 ? wm : wl) + j*EMB_;
        float a0=0,a1=0,a2=0,a3=0;
        for (int i = 0; i < EMB_; i += 4) {
            a0 += st[i]*w[i];   a1 += st[i+1]*w[i+1];
            a2 += st[i+2]*w[i+2]; a3 += st[i+3]*w[i+3];
        }
        sv[tid] = (a0+a1)+(a2+a3) + (tid < 40 ? bm[j] : bl[j]);
    }
    __syncthreads();
    {
        int which = tid >> 6;
        int e = tid & 63, du = e >> 3, dv = e & 7;
        const float* S = sv + which*40;
        float acc = 0.f;
        #pragma unroll
        for (int p = 0; p < 8; p++)
            #pragma unroll
            for (int q = 0; q < 5; q++) {
                float wq = (q == 0 || q == 4) ? 1.f : 2.f;
                acc += wq * S[p*5 + q] * c_c8[(p*du + q*dv) & 7];
            }
        kk[which][e] = acc * (1.f/64.f);
    }
    __syncthreads();
    // scatter circulant: KcT[f][e] = k[(eu-fu)&7][(ev-fv)&7]
    for (int idx = tid; idx < 8192; idx += 128) {
        int which = idx >> 12, r = idx & 4095;
        int f = r >> 6, e = r & 63;
        int du = ((e >> 3) - (f >> 3)) & 7;
        int dv = ((e & 7) - (f & 7)) & 7;
        float val = kk[which][du*8 + dv];
        if (which == 0) g_kc1[b*4096 + r] = val;
        else            g_kc2[b*4096 + r] = val;
    }
}

// ---------------- GroupNorm stats ----------------
__global__ __launch_bounds__(256) void k_stats(const float* __restrict__ x, float* __restrict__ st)
{
    int bg = blockIdx.x, tid = threadIdx.x;
    const float* p = x + (size_t)bg * 24576;
    float s = 0.f, s2 = 0.f;
    for (int i = tid; i < 24576; i += 256) { float v = p[i]; s += v; s2 += v*v; }
    __shared__ float rs[8], rq[8];
    for (int o = 16; o; o >>= 1) {
        s  += __shfl_down_sync(0xffffffffu, s,  o);
        s2 += __shfl_down_sync(0xffffffffu, s2, o);
    }
    if ((tid & 31) == 0) { rs[tid>>5] = s; rq[tid>>5] = s2; }
    __syncthreads();
    if (tid == 0) {
        float S = 0.f, Q = 0.f;
        for (int i = 0; i < 8; i++) { S += rs[i]; Q += rq[i]; }
        float mu = S / 24576.f;
        float var = Q / 24576.f - mu*mu;
        st[bg*2]   = mu;
        st[bg*2+1] = rsqrtf(var + 1e-5f);
    }
}

// ---------------- GN apply + AdaFM as circulant GEMM, BCHW -> BHWC ----------------
__global__ __launch_bounds__(256) void k_gn_ada(
    const float* __restrict__ x, const float* __restrict__ st,
    const float* __restrict__ gma, const float* __restrict__ bta,
    const float* __restrict__ kcT, float* __restrict__ out)
{
    int pi = blockIdx.x, chunk = blockIdx.y, b = blockIdx.z;
    int pr = pi >> 3, pc = pi & 7;
    int tid = threadIdx.x;
    __shared__ float Ks[4096];       // [f][e]
    __shared__ float spT[64*34];     // [f][ch] padded (even stride -> ull ok)
    const float4* kc4 = (const float4*)(kcT + b*4096);
    for (int i = tid; i < 1024; i += 256) ((float4*)Ks)[i] = kc4[i];
    int ch0 = chunk * 32;
    for (int i = tid; i < 2048; i += 256) {
        int chL = i >> 6, rc = i & 63, r = rc >> 3, cc = rc & 7;
        int ch = ch0 + chL, g = ch / 6;
        float mu = st[(b*32+g)*2], rsd = st[(b*32+g)*2 + 1];
        float v = x[(size_t)(b*192 + ch)*4096 + (pr*8 + r)*64 + pc*8 + cc];
        spT[rc*34 + chL] = (v - mu) * rsd * gma[ch] + bta[ch];
    }
    __syncthreads();
    int e0 = (tid & 15) * 4, c0 = (tid >> 4) * 2;
    ull acc2[4] = {0ULL, 0ULL, 0ULL, 0ULL};
    #pragma unroll 4
    for (int f = 0; f < 64; f++) {
        float4 a4 = *(const float4*)&Ks[f*64 + e0];
        ull b2 = *(const ull*)&spT[f*34 + c0];
        float as[4] = {a4.x, a4.y, a4.z, a4.w};
        #pragma unroll
        for (int i = 0; i < 4; i++) fma2(acc2[i], dup2(as[i]), b2);
    }
    #pragma unroll
    for (int i = 0; i < 4; i++) {
        float lo, hi;
        unpk(acc2[i], lo, hi);
        int e = e0 + i, u = e >> 3, v = e & 7;
        int row = pr*8 + u, col = pc*8 + v;
        float2 w2 = make_float2(lo, hi);
        *(float2*)&out[((size_t)(b*64 + row)*64 + col)*192 + ch0 + c0] = w2;
    }
}

// ---------------- fused window attention (FFMA2, K-major activations) ----------------
// grid 2048, block 256
__global__ __launch_bounds__(256) void k_attn(
    const float* __restrict__ h, const float* __restrict__ xin,
    const float* __restrict__ qkvT, const float* __restrict__ qkv_b,
    const float* __restrict__ rpb, const float* __restrict__ pT,
    const float* __restrict__ proj_b, float* __restrict__ xa)
{
    extern __shared__ float sm[];
    float* xwT  = sm;              // [192][64]   12288  (k-major tokens)
    float* wb   = xwT + 12288;     // [192][96]   18432
    float* qT   = wb + 18432;      // [32][64]    2048
    float* kT   = qT + 2048;       // [32][64]    2048
    float* vS   = kT + 2048;       // [64][32]    2048
    float* A    = vS + 2048;       // [64][65]    4160
    float* outT = A + 4160;        // [192][64]   12288
    float* rb   = outT + 12288;    // 240
    __shared__ int lab[64];

    int tid = threadIdx.x;
    int b = blockIdx.x >> 6, win = blockIdx.x & 63;
    int wr = win >> 3, wc = win & 7;

    // stage tokens k-major via 4x4 register transpose (roll folded into index)
    #pragma unroll
    for (int it = 0; it < 3; it++) {
        int idx = it*256 + tid;          // 0..767
        int n4 = idx & 15, k4 = idx >> 4; // k4: 0..47
        float4 r4[4];
        #pragma unroll
        for (int r = 0; r < 4; r++) {
            int n = n4*4 + r;
            int rr = (wr*8 + (n >> 3) + 4) & 63;
            int cc = (wc*8 + (n & 7) + 4) & 63;
            r4[r] = *(const float4*)&h[((size_t)((b*64 + rr)*64 + cc))*192 + k4*4];
        }
        #pragma unroll
        for (int j = 0; j < 4; j++) {
            float4 o;
            o.x = ((const float*)&r4[0])[j];
            o.y = ((const float*)&r4[1])[j];
            o.z = ((const float*)&r4[2])[j];
            o.w = ((const float*)&r4[3])[j];
            *(float4*)&xwT[(k4*4 + j)*64 + n4*4] = o;
        }
    }
    if (tid < 64) {
        int r = wr*8 + (tid >> 3), c = wc*8 + (tid & 7);
        int ra = (r < 56) ? 0 : (r < 60 ? 1 : 2);
        int ca = (c < 56) ? 0 : (c < 60 ? 1 : 2);
        lab[tid] = ra*3 + ca;
    }

    int mt = tid & 15, nt = tid >> 4;
    int m0 = mt * 4;

    for (int head = 0; head < 6; head++) {
        __syncthreads();
        {
            const float4* srcw = (const float4*)(qkvT + head*18432);
            float4* dstw = (float4*)wb;
            #pragma unroll
            for (int i = 0; i < 18; i++) dstw[tid + i*256] = srcw[tid + i*256];
        }
        if (tid < 225) rb[tid] = rpb[tid*6 + head];
        __syncthreads();

        // ---- QKV: 64x96, K=192, tile 4x6 (3 packed pairs) ----
        {
            int j0 = nt * 6;
            ull acc2[4][3];
            #pragma unroll
            for (int i = 0; i < 4; i++)
                #pragma unroll
                for (int j = 0; j < 3; j++) acc2[i][j] = 0ULL;
            #pragma unroll 2
            for (int k2 = 0; k2 < 192; k2++) {
                float4 xv4 = *(const float4*)&xwT[k2*64 + m0];
                const float* wrow = &wb[k2*96 + j0];
                ull w0 = *(const ull*)&wrow[0];
                ull w1 = *(const ull*)&wrow[2];
                ull w2 = *(const ull*)&wrow[4];
                float xs[4] = {xv4.x, xv4.y, xv4.z, xv4.w};
                #pragma unroll
                for (int i = 0; i < 4; i++) {
                    ull xd = dup2(xs[i]);
                    fma2(acc2[i][0], xd, w0);
                    fma2(acc2[i][1], xd, w1);
                    fma2(acc2[i][2], xd, w2);
                }
            }
            #pragma unroll
            for (int jp = 0; jp < 3; jp++) {
                #pragma unroll
                for (int i = 0; i < 4; i++) {
                    float lo, hi;
                    unpk(acc2[i][jp], lo, hi);
                    float vals[2] = {lo, hi};
                    #pragma unroll
                    for (int s = 0; s < 2; s++) {
                        int j = j0 + jp*2 + s, kind = j >> 5, d = j & 31;
                        float val = vals[s] + qkv_b[kind*192 + head*32 + d];
                        if (kind == 0)      qT[d*64 + m0 + i] = val * SCALE_;
                        else if (kind == 1) kT[d*64 + m0 + i] = val;
                        else                vS[(m0+i)*32 + d] = val;
                    }
                }
            }
        }
        __syncthreads();

        // ---- logits: 64x64, K=32, tile 4x4 (2 packed pairs) ----
        {
            int n0 = mt * 4, mm0 = nt * 4;
            ull acc2[4][2];
            #pragma unroll
            for (int i = 0; i < 4; i++) { acc2[i][0] = 0ULL; acc2[i][1] = 0ULL; }
            #pragma unroll 4
            for (int d = 0; d < 32; d++) {
                float4 qv = *(const float4*)&qT[d*64 + n0];
                float4 kv = *(const float4*)&kT[d*64 + mm0];
                ull k01 = ((const ull*)&kv)[0];
                ull k23 = ((const ull*)&kv)[1];
                float qs[4] = {qv.x, qv.y, qv.z, qv.w};
                #pragma unroll
                for (int i = 0; i < 4; i++) {
                    ull qd = dup2(qs[i]);
                    fma2(acc2[i][0], qd, k01);
                    fma2(acc2[i][1], qd, k23);
                }
            }
            #pragma unroll
            for (int i = 0; i < 4; i++) {
                float v01[2], v23[2];
                unpk(acc2[i][0], v01[0], v01[1]);
                unpk(acc2[i][1], v23[0], v23[1]);
                float vals[4] = {v01[0], v01[1], v23[0], v23[1]};
                int n = n0 + i;
                #pragma unroll
                for (int j = 0; j < 4; j++) {
                    int m = mm0 + j;
                    int di = (n >> 3) - (m >> 3) + 7;
                    int dj = (n & 7) - (m & 7) + 7;
                    float v = vals[j] + rb[di*15 + dj];
                    if (lab[n] != lab[m]) v -= 100.f;
                    A[n*65 + m] = v;
                }
            }
        }
        __syncthreads();

        // ---- softmax: 4 lanes per row ----
        {
            int r = tid >> 2, q = tid & 3;
            float* ar = A + r*65;
            int mlo = q*16;
            float mx = ar[mlo];
            #pragma unroll 5
            for (int m2 = 1; m2 < 16; m2++) mx = fmaxf(mx, ar[mlo + m2]);
            mx = fmaxf(mx, __shfl_xor_sync(0xffffffffu, mx, 1, 4));
            mx = fmaxf(mx, __shfl_xor_sync(0xffffffffu, mx, 2, 4));
            float s = 0.f;
            #pragma unroll 4
            for (int m2 = 0; m2 < 16; m2++) {
                float ex = expf(ar[mlo + m2] - mx);
                ar[mlo + m2] = ex;
                s += ex;
            }
            s += __shfl_xor_sync(0xffffffffu, s, 1, 4);
            s += __shfl_xor_sync(0xffffffffu, s, 2, 4);
            float inv = 1.f / s;
            #pragma unroll 4
            for (int m2 = 0; m2 < 16; m2++) ar[mlo + m2] *= inv;
        }
        __syncthreads();

        // ---- AV: 64x32, K=64, tile 4x2 (1 packed pair) ----
        {
            int n0 = mt * 4, d0 = nt * 2;
            ull acc2[4] = {0ULL, 0ULL, 0ULL, 0ULL};
            #pragma unroll 4
            for (int m2 = 0; m2 < 64; m2++) {
                ull vv = *(const ull*)&vS[m2*32 + d0];
                #pragma unroll
                for (int i = 0; i < 4; i++)
                    fma2(acc2[i], dup2(A[(n0+i)*65 + m2]), vv);
            }
            #pragma unroll
            for (int i = 0; i < 4; i++) {
                float lo, hi;
                unpk(acc2[i], lo, hi);
                outT[(head*32 + d0    )*64 + n0 + i] = lo;
                outT[(head*32 + d0 + 1)*64 + n0 + i] = hi;
            }
        }
    }

    // ---- proj + residual + reverse roll (2 chunks of 96 cols) ----
    for (int cch = 0; cch < 2; cch++) {
        __syncthreads();
        {
            const float* srcp = pT + cch*96;
            for (int i4 = tid; i4 < 4608; i4 += 256) {
                int i = i4 / 24, j4 = i4 % 24;
                *(float4*)&wb[i*96 + j4*4] = *(const float4*)&srcp[i*192 + j4*4];
            }
        }
        __syncthreads();
        int j0 = nt * 6;
        ull acc2[4][3];
        #pragma unroll
        for (int i = 0; i < 4; i++)
            #pragma unroll
            for (int j = 0; j < 3; j++) acc2[i][j] = 0ULL;
        #pragma unroll 2
        for (int k2 = 0; k2 < 192; k2++) {
            float4 xv4 = *(const float4*)&outT[k2*64 + m0];
            const float* wrow = &wb[k2*96 + j0];
            ull w0 = *(const ull*)&wrow[0];
            ull w1 = *(const ull*)&wrow[2];
            ull w2 = *(const ull*)&wrow[4];
            float xs[4] = {xv4.x, xv4.y, xv4.z, xv4.w};
            #pragma unroll
            for (int i = 0; i < 4; i++) {
                ull xd = dup2(xs[i]);
                fma2(acc2[i][0], xd, w0);
                fma2(acc2[i][1], xd, w1);
                fma2(acc2[i][2], xd, w2);
            }
        }
        #pragma unroll
        for (int jp = 0; jp < 3; jp++) {
            #pragma unroll
            for (int i = 0; i < 4; i++) {
                float lo, hi;
                unpk(acc2[i][jp], lo, hi);
                float vals[2] = {lo, hi};
                int n = m0 + i;
                int fr = (wr*8 + (n >> 3) + 4) & 63;
                int fc = (wc*8 + (n & 7) + 4) & 63;
                #pragma unroll
                for (int s = 0; s < 2; s++) {
                    int co = cch*96 + j0 + jp*2 + s;
                    size_t gi = ((size_t)((b*192 + co)*64 + fr))*64 + fc;
                    xa[gi] = xin[gi] + vals[s] + proj_b[co];
                }
            }
        }
    }
}

// ---------------- fused MLP (FFMA2, K-major activations) ----------------
// grid 2048, block 256
__global__ __launch_bounds__(256) void k_mlp(
    const float* __restrict__ h2, const float* __restrict__ xa,
    const float* __restrict__ f1T, const float* __restrict__ fc1_b,
    const float* __restrict__ f2T, const float* __restrict__ fc2_b,
    float* __restrict__ out)
{
    extern __shared__ float sm[];
    float* xtT  = sm;            // [192][64]  12288 (k-major)
    float* hidT = xtT + 12288;   // [96][64]   6144
    float* wb   = hidT + 6144;   // 18432
    int tid = threadIdx.x;
    int b = blockIdx.x >> 6, hh = blockIdx.x & 63;
    const float* src = h2 + ((size_t)(b*64 + hh))*64*192;

    // stage tokens k-major via 4x4 register transpose
    #pragma unroll
    for (int it = 0; it < 3; it++) {
        int idx = it*256 + tid;
        int n4 = idx & 15, k4 = idx >> 4;
        float4 r4[4];
        #pragma unroll
        for (int r = 0; r < 4; r++)
            r4[r] = *(const float4*)&src[(n4*4 + r)*192 + k4*4];
        #pragma unroll
        for (int j = 0; j < 4; j++) {
            float4 o;
            o.x = ((const float*)&r4[0])[j];
            o.y = ((const float*)&r4[1])[j];
            o.z = ((const float*)&r4[2])[j];
            o.w = ((const float*)&r4[3])[j];
            *(float4*)&xtT[(k4*4 + j)*64 + n4*4] = o;
        }
    }

    int mt = tid & 15, ct = tid >> 4;
    int m0 = mt * 4;
    int co0 = ct * 12;
    ull oacc[4][6];
    #pragma unroll
    for (int i = 0; i < 4; i++)
        #pragma unroll
        for (int j = 0; j < 6; j++) oacc[i][j] = 0ULL;

    for (int chunk = 0; chunk < 8; chunk++) {
        __syncthreads();
        for (int i4 = tid; i4 < 4608; i4 += 256) {
            int k = i4 / 24, j4 = i4 % 24;
            *(float4*)&wb[k*96 + j4*4] = *(const float4*)&f1T[k*768 + chunk*96 + j4*4];
        }
        __syncthreads();
        // GEMM1: 64x96, K=192, tile 4x6 -> gelu -> hidT
        {
            int j0 = ct * 6;
            ull acc2[4][3];
            #pragma unroll
            for (int i = 0; i < 4; i++)
                #pragma unroll
                for (int j = 0; j < 3; j++) acc2[i][j] = 0ULL;
            #pragma unroll 2
            for (int k2 = 0; k2 < 192; k2++) {
                float4 xv4 = *(const float4*)&xtT[k2*64 + m0];
                const float* wrow = &wb[k2*96 + j0];
                ull w0 = *(const ull*)&wrow[0];
                ull w1 = *(const ull*)&wrow[2];
                ull w2 = *(const ull*)&wrow[4];
                float xs[4] = {xv4.x, xv4.y, xv4.z, xv4.w};
                #pragma unroll
                for (int i = 0; i < 4; i++) {
                    ull xd = dup2(xs[i]);
                    fma2(acc2[i][0], xd, w0);
                    fma2(acc2[i][1], xd, w1);
                    fma2(acc2[i][2], xd, w2);
                }
            }
            #pragma unroll
            for (int jp = 0; jp < 3; jp++) {
                #pragma unroll
                for (int i = 0; i < 4; i++) {
                    float lo, hi;
                    unpk(acc2[i][jp], lo, hi);
                    float vals[2] = {lo, hi};
                    #pragma unroll
                    for (int s = 0; s < 2; s++) {
                        int j = j0 + jp*2 + s;
                        float val = vals[s] + fc1_b[chunk*96 + j];
                        val = 0.5f * val * (1.f + erff(val * 0.70710678118654752f));
                        hidT[j*64 + m0 + i] = val;
                    }
                }
            }
        }
        __syncthreads();
        {
            const float4* s4 = (const float4*)(f2T + chunk*96*192);
            float4* d4 = (float4*)wb;
            #pragma unroll
            for (int i = 0; i < 18; i++) d4[tid + i*256] = s4[tid + i*256];
        }
        __syncthreads();
        // GEMM2: 64x192, K=96, tile 4x12 (6 packed pairs), accumulate
        #pragma unroll 2
        for (int jL = 0; jL < 96; jL++) {
            float4 xv4 = *(const float4*)&hidT[jL*64 + m0];
            const float* wrow = &wb[jL*192 + co0];
            float4 wA = *(const float4*)&wrow[0];
            float4 wBv = *(const float4*)&wrow[4];
            float4 wC = *(const float4*)&wrow[8];
            ull wp[6] = {((const ull*)&wA)[0], ((const ull*)&wA)[1],
                         ((const ull*)&wBv)[0], ((const ull*)&wBv)[1],
                         ((const ull*)&wC)[0], ((const ull*)&wC)[1]};
            float xs[4] = {xv4.x, xv4.y, xv4.z, xv4.w};
            #pragma unroll
            for (int i = 0; i < 4; i++) {
                ull xd = dup2(xs[i]);
                #pragma unroll
                for (int j = 0; j < 6; j++) fma2(oacc[i][j], xd, wp[j]);
            }
        }
    }
    // epilogue: bias + residual, BCHW
    #pragma unroll
    for (int j = 0; j < 6; j++) {
        #pragma unroll
        for (int i = 0; i < 4; i++) {
            float lo, hi;
            unpk(oacc[i][j], lo, hi);
            float vals[2] = {lo, hi};
            #pragma unroll
            for (int s = 0; s < 2; s++) {
                int co = co0 + j*2 + s;
                size_t gi = ((size_t)((b*192 + co)*64 + hh))*64 + m0 + i;
                out[gi] = xa[gi] + vals[s] + fc2_b[co];
            }
        }
    }
}

// ---------------- launcher ----------------
extern "C" void kernel_launch(void* const* d_in, const int* in_sizes, int n_in,
                              void* d_out, int out_size)
{
    const float* x        = (const float*)d_in[0];
    const float* t        = (const float*)d_in[1];
    const float* n1_w     = (const float*)d_in[2];
    const float* n1_b     = (const float*)d_in[3];
    const float* qkv_w    = (const float*)d_in[4];
    const float* qkv_b    = (const float*)d_in[5];
    const float* rpb      = (const float*)d_in[6];
    const float* proj_w   = (const float*)d_in[7];
    const float* proj_b   = (const float*)d_in[8];
    const float* n2_w     = (const float*)d_in[9];
    const float* n2_b     = (const float*)d_in[10];
    const float* fc1_w    = (const float*)d_in[11];
    const float* fc1_b    = (const float*)d_in[12];
    const float* fc2_w    = (const float*)d_in[13];
    const float* fc2_b    = (const float*)d_in[14];
    const float* ada_msa_w = (const float*)d_in[15];
    const float* ada_msa_b = (const float*)d_in[16];
    const float* ada_mlp_w = (const float*)d_in[17];
    const float* ada_mlp_b = (const float*)d_in[18];
    float* out = (float*)d_out;

    float *p_h, *p_xa, *p_h2, *p_kc1, *p_kc2, *p_st1, *p_st2;
    float *p_qkvT, *p_pT, *p_f1T, *p_f2T;
    cudaGetSymbolAddress((void**)&p_h,    g_h);
    cudaGetSymbolAddress((void**)&p_xa,   g_xa);
    cudaGetSymbolAddress((void**)&p_h2,   g_h2);
    cudaGetSymbolAddress((void**)&p_kc1,  g_kc1);
    cudaGetSymbolAddress((void**)&p_kc2,  g_kc2);
    cudaGetSymbolAddress((void**)&p_st1,  g_st1);
    cudaGetSymbolAddress((void**)&p_st2,  g_st2);
    cudaGetSymbolAddress((void**)&p_qkvT, g_qkvT);
    cudaGetSymbolAddress((void**)&p_pT,   g_pT);
    cudaGetSymbolAddress((void**)&p_f1T,  g_f1T);
    cudaGetSymbolAddress((void**)&p_f2T,  g_f2T);

    cudaFuncSetAttribute(k_attn, cudaFuncAttributeMaxDynamicSharedMemorySize, 214208);
    cudaFuncSetAttribute(k_mlp,  cudaFuncAttributeMaxDynamicSharedMemorySize, 147456);

    k_prep<<<1728, 256>>>(qkv_w, proj_w, fc1_w, fc2_w);
    k0_ada<<<32, 128>>>(t, ada_msa_w, ada_msa_b, ada_mlp_w, ada_mlp_b);
    k_stats<<<1024, 256>>>(x, p_st1);
    k_gn_ada<<<dim3(64, 6, 32), 256>>>(x, p_st1, n1_w, n1_b, p_kc1, p_h);
    k_attn<<<2048, 256, 214208>>>(p_h, x, p_qkvT, qkv_b, rpb, p_pT, proj_b, p_xa);
    k_stats<<<1024, 256>>>(p_xa, p_st2);
    k_gn_ada<<<dim3(64, 6, 32), 256>>>(p_xa, p_st2, n2_w, n2_b, p_kc2, p_h2);
    k_mlp<<<2048, 256, 147456>>>(p_h2, p_xa, p_f1T, fc1_b, p_f2T, fc2_b, out);
}

// round 12
// speedup vs baseline: 4.3582x; 1.0354x over previous
#include <cuda_runtime.h>
#include <math.h>

#define B_   32
#define EMB_ 640
#define SCALE_ 0.17677669529663688f  // 1/sqrt(32)

typedef unsigned long long ull;

// ---------------- packed f32x2 helpers (FFMA2 path) ----------------
__device__ __forceinline__ ull dup2(float x) {
    ull r; asm("mov.b64 %0, {%1, %1};" : "=l"(r) : "f"(x)); return r;
}
__device__ __forceinline__ void fma2(ull& d, ull a, ull b) {
    asm("fma.rn.f32x2 %0, %1, %2, %0;" : "+l"(d) : "l"(a), "l"(b));
}
__device__ __forceinline__ void unpk(ull v, float& lo, float& hi) {
    asm("mov.b64 {%0, %1}, %2;" : "=f"(lo), "=f"(hi) : "l"(v));
}

// ---------------- scratch ----------------
__device__ float g_h  [32*64*64*192];   // BHWC after GN1+adafm
__device__ float g_xa [32*192*64*64];   // BCHW after attention residual
__device__ float g_h2 [32*64*64*192];   // BHWC after GN2+adafm
__device__ float g_kc1[32*4096];        // circulant KcT[f][e] per batch (msa)
__device__ float g_kc2[32*4096];        // (mlp)
__device__ float g_st1[32*32*2];
__device__ float g_st2[32*32*2];
__device__ float g_qkvT[6*192*96];      // [head][k=192][j]
__device__ float g_pT  [192*192];       // [k][co]
__device__ float g_f1T [192*768];       // [k][j]
__device__ float g_f2T [768*192];       // [j][co]

__constant__ float c_c8[8] = {1.f, 0.70710678118654752f, 0.f, -0.70710678118654752f,
                              -1.f, -0.70710678118654752f, 0.f, 0.70710678118654752f};

// ---------------- weight transposition ----------------
__global__ __launch_bounds__(256) void k_prep(
    const float* __restrict__ qkv_w, const float* __restrict__ proj_w,
    const float* __restrict__ fc1_w, const float* __restrict__ fc2_w)
{
    int idx = blockIdx.x * 256 + threadIdx.x;
    if (idx < 110592) {
        int h = idx / 18432, r = idx % 18432;
        int i = r / 96, j = r % 96;
        int kind = j >> 5, d = j & 31;
        g_qkvT[idx] = qkv_w[(kind*192 + h*32 + d)*192 + i];
    } else if (idx < 147456) {
        int r = idx - 110592;
        int i = r / 192, co = r % 192;
        g_pT[r] = proj_w[co*192 + i];
    } else if (idx < 294912) {
        int r = idx - 147456;
        int i = r / 768, j = r % 768;
        g_f1T[r] = fc1_w[j*192 + i];
    } else if (idx < 442368) {
        int r = idx - 294912;
        int j = r / 192, co = r % 192;
        g_f2T[r] = fc2_w[co*768 + j];
    }
}

// ---------------- K0: silu(t) -> adafm kernels -> circulant matrices ----------------
__global__ __launch_bounds__(128) void k0_ada(
    const float* __restrict__ t,
    const float* __restrict__ wm, const float* __restrict__ bm,
    const float* __restrict__ wl, const float* __restrict__ bl)
{
    int b = blockIdx.x, tid = threadIdx.x;
    __shared__ float st[EMB_];
    __shared__ float sv[80];
    __shared__ float kk[2][64];
    for (int i = tid; i < EMB_; i += 128) {
        float v = t[b*EMB_ + i];
        st[i] = v / (1.f + expf(-v));
    }
    __syncthreads();
    if (tid < 80) {
        int j = tid % 40;
        const float* w = (tid < 40 ? wm : wl) + j*EMB_;
        float a0=0,a1=0,a2=0,a3=0;
        for (int i = 0; i < EMB_; i += 4) {
            a0 += st[i]*w[i];   a1 += st[i+1]*w[i+1];
            a2 += st[i+2]*w[i+2]; a3 += st[i+3]*w[i+3];
        }
        sv[tid] = (a0+a1)+(a2+a3) + (tid < 40 ? bm[j] : bl[j]);
    }
    __syncthreads();
    {
        int which = tid >> 6;
        int e = tid & 63, du = e >> 3, dv = e & 7;
        const float* S = sv + which*40;
        float acc = 0.f;
        #pragma unroll
        for (int p = 0; p < 8; p++)
            #pragma unroll
            for (int q = 0; q < 5; q++) {
                float wq = (q == 0 || q == 4) ? 1.f : 2.f;
                acc += wq * S[p*5 + q] * c_c8[(p*du + q*dv) & 7];
            }
        kk[which][e] = acc * (1.f/64.f);
    }
    __syncthreads();
    // scatter circulant: KcT[f][e] = k[(eu-fu)&7][(ev-fv)&7]
    for (int idx = tid; idx < 8192; idx += 128) {
        int which = idx >> 12, r = idx & 4095;
        int f = r >> 6, e = r & 63;
        int du = ((e >> 3) - (f >> 3)) & 7;
        int dv = ((e & 7) - (f & 7)) & 7;
        float val = kk[which][du*8 + dv];
        if (which == 0) g_kc1[b*4096 + r] = val;
        else            g_kc2[b*4096 + r] = val;
    }
}

// ---------------- GroupNorm stats ----------------
__global__ __launch_bounds__(256) void k_stats(const float* __restrict__ x, float* __restrict__ st)
{
    int bg = blockIdx.x, tid = threadIdx.x;
    const float* p = x + (size_t)bg * 24576;
    float s = 0.f, s2 = 0.f;
    for (int i = tid; i < 24576; i += 256) { float v = p[i]; s += v; s2 += v*v; }
    __shared__ float rs[8], rq[8];
    for (int o = 16; o; o >>= 1) {
        s  += __shfl_down_sync(0xffffffffu, s,  o);
        s2 += __shfl_down_sync(0xffffffffu, s2, o);
    }
    if ((tid & 31) == 0) { rs[tid>>5] = s; rq[tid>>5] = s2; }
    __syncthreads();
    if (tid == 0) {
        float S = 0.f, Q = 0.f;
        for (int i = 0; i < 8; i++) { S += rs[i]; Q += rq[i]; }
        float mu = S / 24576.f;
        float var = Q / 24576.f - mu*mu;
        st[bg*2]   = mu;
        st[bg*2+1] = rsqrtf(var + 1e-5f);
    }
}

// ---------------- GN apply + AdaFM circulant GEMM: one block per (patch, b) ----------------
__global__ __launch_bounds__(256) void k_gn_ada(
    const float* __restrict__ x, const float* __restrict__ st,
    const float* __restrict__ gma, const float* __restrict__ bta,
    const float* __restrict__ kcT, float* __restrict__ out)
{
    extern __shared__ float smg[];
    float* Ks  = smg;          // [f][e] 4096
    float* spT = Ks + 4096;    // [f=64][c=192 pad 194] = 12416
    int pi = blockIdx.x, b = blockIdx.y;
    int pr = pi >> 3, pc = pi & 7;
    int tid = threadIdx.x;
    const float4* kc4 = (const float4*)(kcT + b*4096);
    #pragma unroll
    for (int i = 0; i < 4; i++) ((float4*)Ks)[tid + i*256] = kc4[tid + i*256];
    for (int i = tid; i < 12288; i += 256) {
        int ch = i >> 6, rc = i & 63;
        int g = ch / 6;
        float mu = st[(b*32+g)*2], rsd = st[(b*32+g)*2 + 1];
        float v = x[(size_t)(b*192 + ch)*4096 + (pr*8 + (rc>>3))*64 + pc*8 + (rc&7)];
        spT[rc*194 + ch] = (v - mu) * rsd * gma[ch] + bta[ch];
    }
    __syncthreads();
    int e0 = (tid & 15) * 4, c0 = (tid >> 4) * 12;
    ull acc2[4][6];
    #pragma unroll
    for (int i = 0; i < 4; i++)
        #pragma unroll
        for (int t = 0; t < 6; t++) acc2[i][t] = 0ULL;
    #pragma unroll 2
    for (int f = 0; f < 64; f++) {
        float4 a4 = *(const float4*)&Ks[f*64 + e0];
        const float* sp = &spT[f*194 + c0];
        ull bv[6];
        #pragma unroll
        for (int t = 0; t < 6; t++) bv[t] = *(const ull*)&sp[t*2];
        float as[4] = {a4.x, a4.y, a4.z, a4.w};
        #pragma unroll
        for (int i = 0; i < 4; i++) {
            ull da = dup2(as[i]);
            #pragma unroll
            for (int t = 0; t < 6; t++) fma2(acc2[i][t], da, bv[t]);
        }
    }
    #pragma unroll
    for (int i = 0; i < 4; i++) {
        int e = e0 + i;
        int row = pr*8 + (e >> 3), col = pc*8 + (e & 7);
        float* op = &out[((size_t)(b*64 + row)*64 + col)*192 + c0];
        #pragma unroll
        for (int q = 0; q < 3; q++) {
            float l0,h0,l1,h1;
            unpk(acc2[i][2*q], l0, h0);
            unpk(acc2[i][2*q+1], l1, h1);
            *(float4*)&op[q*4] = make_float4(l0, h0, l1, h1);
        }
    }
}

// ---------------- fused window attention (FFMA2, K-major activations) ----------------
// grid 2048, block 256   (identical to the R6 passing version)
__global__ __launch_bounds__(256) void k_attn(
    const float* __restrict__ h, const float* __restrict__ xin,
    const float* __restrict__ qkvT, const float* __restrict__ qkv_b,
    const float* __restrict__ rpb, const float* __restrict__ pT,
    const float* __restrict__ proj_b, float* __restrict__ xa)
{
    extern __shared__ float sm[];
    float* xwT  = sm;              // [192][64]   12288  (k-major tokens)
    float* wb   = xwT + 12288;     // [192][96]   18432
    float* qT   = wb + 18432;      // [32][64]    2048
    float* kT   = qT + 2048;       // [32][64]    2048
    float* vS   = kT + 2048;       // [64][32]    2048
    float* A    = vS + 2048;       // [64][65]    4160
    float* outT = A + 4160;        // [192][64]   12288
    float* rb   = outT + 12288;    // 240
    __shared__ int lab[64];

    int tid = threadIdx.x;
    int b = blockIdx.x >> 6, win = blockIdx.x & 63;
    int wr = win >> 3, wc = win & 7;

    // stage tokens k-major via 4x4 register transpose (roll folded into index)
    #pragma unroll
    for (int it = 0; it < 3; it++) {
        int idx = it*256 + tid;          // 0..767
        int n4 = idx & 15, k4 = idx >> 4; // k4: 0..47
        float4 r4[4];
        #pragma unroll
        for (int r = 0; r < 4; r++) {
            int n = n4*4 + r;
            int rr = (wr*8 + (n >> 3) + 4) & 63;
            int cc = (wc*8 + (n & 7) + 4) & 63;
            r4[r] = *(const float4*)&h[((size_t)((b*64 + rr)*64 + cc))*192 + k4*4];
        }
        #pragma unroll
        for (int j = 0; j < 4; j++) {
            float4 o;
            o.x = ((const float*)&r4[0])[j];
            o.y = ((const float*)&r4[1])[j];
            o.z = ((const float*)&r4[2])[j];
            o.w = ((const float*)&r4[3])[j];
            *(float4*)&xwT[(k4*4 + j)*64 + n4*4] = o;
        }
    }
    if (tid < 64) {
        int r = wr*8 + (tid >> 3), c = wc*8 + (tid & 7);
        int ra = (r < 56) ? 0 : (r < 60 ? 1 : 2);
        int ca = (c < 56) ? 0 : (c < 60 ? 1 : 2);
        lab[tid] = ra*3 + ca;
    }

    int mt = tid & 15, nt = tid >> 4;
    int m0 = mt * 4;

    for (int head = 0; head < 6; head++) {
        __syncthreads();
        {
            const float4* srcw = (const float4*)(qkvT + head*18432);
            float4* dstw = (float4*)wb;
            #pragma unroll
            for (int i = 0; i < 18; i++) dstw[tid + i*256] = srcw[tid + i*256];
        }
        if (tid < 225) rb[tid] = rpb[tid*6 + head];
        __syncthreads();

        // ---- QKV: 64x96, K=192, tile 4x6 (3 packed pairs) ----
        {
            int j0 = nt * 6;
            ull acc2[4][3];
            #pragma unroll
            for (int i = 0; i < 4; i++)
                #pragma unroll
                for (int j = 0; j < 3; j++) acc2[i][j] = 0ULL;
            #pragma unroll 2
            for (int k2 = 0; k2 < 192; k2++) {
                float4 xv4 = *(const float4*)&xwT[k2*64 + m0];
                const float* wrow = &wb[k2*96 + j0];
                ull w0 = *(const ull*)&wrow[0];
                ull w1 = *(const ull*)&wrow[2];
                ull w2 = *(const ull*)&wrow[4];
                float xs[4] = {xv4.x, xv4.y, xv4.z, xv4.w};
                #pragma unroll
                for (int i = 0; i < 4; i++) {
                    ull xd = dup2(xs[i]);
                    fma2(acc2[i][0], xd, w0);
                    fma2(acc2[i][1], xd, w1);
                    fma2(acc2[i][2], xd, w2);
                }
            }
            #pragma unroll
            for (int jp = 0; jp < 3; jp++) {
                #pragma unroll
                for (int i = 0; i < 4; i++) {
                    float lo, hi;
                    unpk(acc2[i][jp], lo, hi);
                    float vals[2] = {lo, hi};
                    #pragma unroll
                    for (int s = 0; s < 2; s++) {
                        int j = j0 + jp*2 + s, kind = j >> 5, d = j & 31;
                        float val = vals[s] + qkv_b[kind*192 + head*32 + d];
                        if (kind == 0)      qT[d*64 + m0 + i] = val * SCALE_;
                        else if (kind == 1) kT[d*64 + m0 + i] = val;
                        else                vS[(m0+i)*32 + d] = val;
                    }
                }
            }
        }
        __syncthreads();

        // ---- logits: 64x64, K=32, tile 4x4 (2 packed pairs) ----
        {
            int n0 = mt * 4, mm0 = nt * 4;
            ull acc2[4][2];
            #pragma unroll
            for (int i = 0; i < 4; i++) { acc2[i][0] = 0ULL; acc2[i][1] = 0ULL; }
            #pragma unroll 4
            for (int d = 0; d < 32; d++) {
                float4 qv = *(const float4*)&qT[d*64 + n0];
                float4 kv = *(const float4*)&kT[d*64 + mm0];
                ull k01 = ((const ull*)&kv)[0];
                ull k23 = ((const ull*)&kv)[1];
                float qs[4] = {qv.x, qv.y, qv.z, qv.w};
                #pragma unroll
                for (int i = 0; i < 4; i++) {
                    ull qd = dup2(qs[i]);
                    fma2(acc2[i][0], qd, k01);
                    fma2(acc2[i][1], qd, k23);
                }
            }
            #pragma unroll
            for (int i = 0; i < 4; i++) {
                float v01[2], v23[2];
                unpk(acc2[i][0], v01[0], v01[1]);
                unpk(acc2[i][1], v23[0], v23[1]);
                float vals[4] = {v01[0], v01[1], v23[0], v23[1]};
                int n = n0 + i;
                #pragma unroll
                for (int j = 0; j < 4; j++) {
                    int m = mm0 + j;
                    int di = (n >> 3) - (m >> 3) + 7;
                    int dj = (n & 7) - (m & 7) + 7;
                    float v = vals[j] + rb[di*15 + dj];
                    if (lab[n] != lab[m]) v -= 100.f;
                    A[n*65 + m] = v;
                }
            }
        }
        __syncthreads();

        // ---- softmax: 4 lanes per row ----
        {
            int r = tid >> 2, q = tid & 3;
            float* ar = A + r*65;
            int mlo = q*16;
            float mx = ar[mlo];
            #pragma unroll 5
            for (int m2 = 1; m2 < 16; m2++) mx = fmaxf(mx, ar[mlo + m2]);
            mx = fmaxf(mx, __shfl_xor_sync(0xffffffffu, mx, 1, 4));
            mx = fmaxf(mx, __shfl_xor_sync(0xffffffffu, mx, 2, 4));
            float s = 0.f;
            #pragma unroll 4
            for (int m2 = 0; m2 < 16; m2++) {
                float ex = expf(ar[mlo + m2] - mx);
                ar[mlo + m2] = ex;
                s += ex;
            }
            s += __shfl_xor_sync(0xffffffffu, s, 1, 4);
            s += __shfl_xor_sync(0xffffffffu, s, 2, 4);
            float inv = 1.f / s;
            #pragma unroll 4
            for (int m2 = 0; m2 < 16; m2++) ar[mlo + m2] *= inv;
        }
        __syncthreads();

        // ---- AV: 64x32, K=64, tile 4x2 (1 packed pair) ----
        {
            int n0 = mt * 4, d0 = nt * 2;
            ull acc2[4] = {0ULL, 0ULL, 0ULL, 0ULL};
            #pragma unroll 4
            for (int m2 = 0; m2 < 64; m2++) {
                ull vv = *(const ull*)&vS[m2*32 + d0];
                #pragma unroll
                for (int i = 0; i < 4; i++)
                    fma2(acc2[i], dup2(A[(n0+i)*65 + m2]), vv);
            }
            #pragma unroll
            for (int i = 0; i < 4; i++) {
                float lo, hi;
                unpk(acc2[i], lo, hi);
                outT[(head*32 + d0    )*64 + n0 + i] = lo;
                outT[(head*32 + d0 + 1)*64 + n0 + i] = hi;
            }
        }
    }

    // ---- proj + residual + reverse roll (2 chunks of 96 cols) ----
    for (int cch = 0; cch < 2; cch++) {
        __syncthreads();
        {
            const float* srcp = pT + cch*96;
            for (int i4 = tid; i4 < 4608; i4 += 256) {
                int i = i4 / 24, j4 = i4 % 24;
                *(float4*)&wb[i*96 + j4*4] = *(const float4*)&srcp[i*192 + j4*4];
            }
        }
        __syncthreads();
        int j0 = nt * 6;
        ull acc2[4][3];
        #pragma unroll
        for (int i = 0; i < 4; i++)
            #pragma unroll
            for (int j = 0; j < 3; j++) acc2[i][j] = 0ULL;
        #pragma unroll 2
        for (int k2 = 0; k2 < 192; k2++) {
            float4 xv4 = *(const float4*)&outT[k2*64 + m0];
            const float* wrow = &wb[k2*96 + j0];
            ull w0 = *(const ull*)&wrow[0];
            ull w1 = *(const ull*)&wrow[2];
            ull w2 = *(const ull*)&wrow[4];
            float xs[4] = {xv4.x, xv4.y, xv4.z, xv4.w};
            #pragma unroll
            for (int i = 0; i < 4; i++) {
                ull xd = dup2(xs[i]);
                fma2(acc2[i][0], xd, w0);
                fma2(acc2[i][1], xd, w1);
                fma2(acc2[i][2], xd, w2);
            }
        }
        #pragma unroll
        for (int jp = 0; jp < 3; jp++) {
            #pragma unroll
            for (int i = 0; i < 4; i++) {
                float lo, hi;
                unpk(acc2[i][jp], lo, hi);
                float vals[2] = {lo, hi};
                int n = m0 + i;
                int fr = (wr*8 + (n >> 3) + 4) & 63;
                int fc = (wc*8 + (n & 7) + 4) & 63;
                #pragma unroll
                for (int s = 0; s < 2; s++) {
                    int co = cch*96 + j0 + jp*2 + s;
                    size_t gi = ((size_t)((b*192 + co)*64 + fr))*64 + fc;
                    xa[gi] = xin[gi] + vals[s] + proj_b[co];
                }
            }
        }
    }
}

// ---------------- fused MLP (FFMA2, K-major activations) ----------------
// grid 2048, block 256   (identical to the R6 passing version)
__global__ __launch_bounds__(256) void k_mlp(
    const float* __restrict__ h2, const float* __restrict__ xa,
    const float* __restrict__ f1T, const float* __restrict__ fc1_b,
    const float* __restrict__ f2T, const float* __restrict__ fc2_b,
    float* __restrict__ out)
{
    extern __shared__ float sm[];
    float* xtT  = sm;            // [192][64]  12288 (k-major)
    float* hidT = xtT + 12288;   // [96][64]   6144
    float* wb   = hidT + 6144;   // 18432
    int tid = threadIdx.x;
    int b = blockIdx.x >> 6, hh = blockIdx.x & 63;
    const float* src = h2 + ((size_t)(b*64 + hh))*64*192;

    // stage tokens k-major via 4x4 register transpose
    #pragma unroll
    for (int it = 0; it < 3; it++) {
        int idx = it*256 + tid;
        int n4 = idx & 15, k4 = idx >> 4;
        float4 r4[4];
        #pragma unroll
        for (int r = 0; r < 4; r++)
            r4[r] = *(const float4*)&src[(n4*4 + r)*192 + k4*4];
        #pragma unroll
        for (int j = 0; j < 4; j++) {
            float4 o;
            o.x = ((const float*)&r4[0])[j];
            o.y = ((const float*)&r4[1])[j];
            o.z = ((const float*)&r4[2])[j];
            o.w = ((const float*)&r4[3])[j];
            *(float4*)&xtT[(k4*4 + j)*64 + n4*4] = o;
        }
    }

    int mt = tid & 15, ct = tid >> 4;
    int m0 = mt * 4;
    int co0 = ct * 12;
    ull oacc[4][6];
    #pragma unroll
    for (int i = 0; i < 4; i++)
        #pragma unroll
        for (int j = 0; j < 6; j++) oacc[i][j] = 0ULL;

    for (int chunk = 0; chunk < 8; chunk++) {
        __syncthreads();
        for (int i4 = tid; i4 < 4608; i4 += 256) {
            int k = i4 / 24, j4 = i4 % 24;
            *(float4*)&wb[k*96 + j4*4] = *(const float4*)&f1T[k*768 + chunk*96 + j4*4];
        }
        __syncthreads();
        // GEMM1: 64x96, K=192, tile 4x6 -> gelu -> hidT
        {
            int j0 = ct * 6;
            ull acc2[4][3];
            #pragma unroll
            for (int i = 0; i < 4; i++)
                #pragma unroll
                for (int j = 0; j < 3; j++) acc2[i][j] = 0ULL;
            #pragma unroll 2
            for (int k2 = 0; k2 < 192; k2++) {
                float4 xv4 = *(const float4*)&xtT[k2*64 + m0];
                const float* wrow = &wb[k2*96 + j0];
                ull w0 = *(const ull*)&wrow[0];
                ull w1 = *(const ull*)&wrow[2];
                ull w2 = *(const ull*)&wrow[4];
                float xs[4] = {xv4.x, xv4.y, xv4.z, xv4.w};
                #pragma unroll
                for (int i = 0; i < 4; i++) {
                    ull xd = dup2(xs[i]);
                    fma2(acc2[i][0], xd, w0);
                    fma2(acc2[i][1], xd, w1);
                    fma2(acc2[i][2], xd, w2);
                }
            }
            #pragma unroll
            for (int jp = 0; jp < 3; jp++) {
                #pragma unroll
                for (int i = 0; i < 4; i++) {
                    float lo, hi;
                    unpk(acc2[i][jp], lo, hi);
                    float vals[2] = {lo, hi};
                    #pragma unroll
                    for (int s = 0; s < 2; s++) {
                        int j = j0 + jp*2 + s;
                        float val = vals[s] + fc1_b[chunk*96 + j];
                        val = 0.5f * val * (1.f + erff(val * 0.70710678118654752f));
                        hidT[j*64 + m0 + i] = val;
                    }
                }
            }
        }
        __syncthreads();
        {
            const float4* s4 = (const float4*)(f2T + chunk*96*192);
            float4* d4 = (float4*)wb;
            #pragma unroll
            for (int i = 0; i < 18; i++) d4[tid + i*256] = s4[tid + i*256];
        }
        __syncthreads();
        // GEMM2: 64x192, K=96, tile 4x12 (6 packed pairs), accumulate
        #pragma unroll 2
        for (int jL = 0; jL < 96; jL++) {
            float4 xv4 = *(const float4*)&hidT[jL*64 + m0];
            const float* wrow = &wb[jL*192 + co0];
            float4 wA = *(const float4*)&wrow[0];
            float4 wBv = *(const float4*)&wrow[4];
            float4 wC = *(const float4*)&wrow[8];
            ull wp[6] = {((const ull*)&wA)[0], ((const ull*)&wA)[1],
                         ((const ull*)&wBv)[0], ((const ull*)&wBv)[1],
                         ((const ull*)&wC)[0], ((const ull*)&wC)[1]};
            float xs[4] = {xv4.x, xv4.y, xv4.z, xv4.w};
            #pragma unroll
            for (int i = 0; i < 4; i++) {
                ull xd = dup2(xs[i]);
                #pragma unroll
                for (int j = 0; j < 6; j++) fma2(oacc[i][j], xd, wp[j]);
            }
        }
    }
    // epilogue: bias + residual, BCHW
    #pragma unroll
    for (int j = 0; j < 6; j++) {
        #pragma unroll
        for (int i = 0; i < 4; i++) {
            float lo, hi;
            unpk(oacc[i][j], lo, hi);
            float vals[2] = {lo, hi};
            #pragma unroll
            for (int s = 0; s < 2; s++) {
                int co = co0 + j*2 + s;
                size_t gi = ((size_t)((b*192 + co)*64 + hh))*64 + m0 + i;
                out[gi] = xa[gi] + vals[s] + fc2_b[co];
            }
        }
    }
}

// ---------------- launcher ----------------
extern "C" void kernel_launch(void* const* d_in, const int* in_sizes, int n_in,
                              void* d_out, int out_size)
{
    const float* x        = (const float*)d_in[0];
    const float* t        = (const float*)d_in[1];
    const float* n1_w     = (const float*)d_in[2];
    const float* n1_b     = (const float*)d_in[3];
    const float* qkv_w    = (const float*)d_in[4];
    const float* qkv_b    = (const float*)d_in[5];
    const float* rpb      = (const float*)d_in[6];
    const float* proj_w   = (const float*)d_in[7];
    const float* proj_b   = (const float*)d_in[8];
    const float* n2_w     = (const float*)d_in[9];
    const float* n2_b     = (const float*)d_in[10];
    const float* fc1_w    = (const float*)d_in[11];
    const float* fc1_b    = (const float*)d_in[12];
    const float* fc2_w    = (const float*)d_in[13];
    const float* fc2_b    = (const float*)d_in[14];
    const float* ada_msa_w = (const float*)d_in[15];
    const float* ada_msa_b = (const float*)d_in[16];
    const float* ada_mlp_w = (const float*)d_in[17];
    const float* ada_mlp_b = (const float*)d_in[18];
    float* out = (float*)d_out;

    float *p_h, *p_xa, *p_h2, *p_kc1, *p_kc2, *p_st1, *p_st2;
    float *p_qkvT, *p_pT, *p_f1T, *p_f2T;
    cudaGetSymbolAddress((void**)&p_h,    g_h);
    cudaGetSymbolAddress((void**)&p_xa,   g_xa);
    cudaGetSymbolAddress((void**)&p_h2,   g_h2);
    cudaGetSymbolAddress((void**)&p_kc1,  g_kc1);
    cudaGetSymbolAddress((void**)&p_kc2,  g_kc2);
    cudaGetSymbolAddress((void**)&p_st1,  g_st1);
    cudaGetSymbolAddress((void**)&p_st2,  g_st2);
    cudaGetSymbolAddress((void**)&p_qkvT, g_qkvT);
    cudaGetSymbolAddress((void**)&p_pT,   g_pT);
    cudaGetSymbolAddress((void**)&p_f1T,  g_f1T);
    cudaGetSymbolAddress((void**)&p_f2T,  g_f2T);

    cudaFuncSetAttribute(k_gn_ada, cudaFuncAttributeMaxDynamicSharedMemorySize, 66048);
    cudaFuncSetAttribute(k_attn, cudaFuncAttributeMaxDynamicSharedMemorySize, 214208);
    cudaFuncSetAttribute(k_mlp,  cudaFuncAttributeMaxDynamicSharedMemorySize, 147456);

    k_prep<<<1728, 256>>>(qkv_w, proj_w, fc1_w, fc2_w);
    k0_ada<<<32, 128>>>(t, ada_msa_w, ada_msa_b, ada_mlp_w, ada_mlp_b);
    k_stats<<<1024, 256>>>(x, p_st1);
    k_gn_ada<<<dim3(64, 32), 256, 66048>>>(x, p_st1, n1_w, n1_b, p_kc1, p_h);
    k_attn<<<2048, 256, 214208>>>(p_h, x, p_qkvT, qkv_b, rpb, p_pT, proj_b, p_xa);
    k_stats<<<1024, 256>>>(p_xa, p_st2);
    k_gn_ada<<<dim3(64, 32), 256, 66048>>>(p_xa, p_st2, n2_w, n2_b, p_kc2, p_h2);
    k_mlp<<<2048, 256, 147456>>>(p_h2, p_xa, p_f1T, fc1_b, p_f2T, fc2_b, out);
}